// round 14
// baseline (speedup 1.0000x reference)
#include <cuda_runtime.h>
#include <math.h>
#include <math_constants.h>

#define SEQ    2048
#define BATCH  2
#define HID    4096
#define NHEADS 32
#define NKV    8
#define HD     128
#define KVD    1024
#define MROWS  (BATCH*SEQ)
#define BIGSZ  16777216
#define MIDSZ  4194304
#define POSSZ  (BATCH*SEQ)

// ln(10000)/64 (displayed theta)
#define ROPE_LN_OVER_HALF 0.14391156831212787f

__device__ float g_Q[MROWS * HID];
__device__ float g_K[MROWS * KVD];
__device__ float g_V[MROWS * KVD];
__device__ float g_O[MROWS * HID];

// [0]=X, [1]=Wq, [2]=Wk, [3]=Wv, [4]=Wo, [5]=position_ids(raw)
__device__ unsigned long long g_ptrs[6];
__device__ int g_pos_is64;

struct InArgs {
    const float* p[8];
    int sz[8];
    int n;
};

__global__ void classify_kernel(InArgs a)
{
    if (threadIdx.x != 0 || blockIdx.x != 0) return;

    int bigs[3]; int nb = 0;
    int mids[2]; int nm = 0;
    int ipos = -1;
    for (int i = 0; i < a.n && i < 8; i++) {
        if (a.sz[i] == BIGSZ && nb < 3) bigs[nb++] = i;
        else if (a.sz[i] == MIDSZ && nm < 2) mids[nm++] = i;
        else if (a.sz[i] == POSSZ && ipos < 0) ipos = i;
    }

    int iX, iWq, iWk, iWv, iWo;
    if (nb == 3 && nm == 2) {
        float avg[3];
        for (int t = 0; t < 3; t++) {
            const float* p = a.p[bigs[t]];
            float s = 0.f;
            for (int j = 0; j < 512; j++) s += fabsf(p[j * 97]);
            avg[t] = s * (1.f / 512.f);
        }
        int hid = 0;
        if (avg[1] > avg[hid]) hid = 1;
        if (avg[2] > avg[hid]) hid = 2;
        int rem[2], c = 0;
        for (int t = 0; t < 3; t++) if (t != hid) rem[c++] = t;
        iX = bigs[hid];
        if (hid == 2) { iWq = bigs[rem[1]]; iWo = bigs[rem[0]]; }   // alphabetical
        else          { iWq = bigs[rem[0]]; iWo = bigs[rem[1]]; }   // dict order
        iWk = mids[0];
        iWv = mids[1];
    } else {
        iX = 0; iWq = 2; iWk = 3; iWv = 4; iWo = 5;
    }

    g_ptrs[0] = (unsigned long long)a.p[iX];
    g_ptrs[1] = (unsigned long long)a.p[iWq];
    g_ptrs[2] = (unsigned long long)a.p[iWk];
    g_ptrs[3] = (unsigned long long)a.p[iWv];
    g_ptrs[4] = (unsigned long long)a.p[iWo];
    g_ptrs[5] = (ipos >= 0) ? (unsigned long long)a.p[ipos] : 0ull;

    int is64 = 0;
    if (ipos >= 0) {
        const int* w = (const int*)a.p[ipos];
        int odd_zero = (w[1] == 0) && (w[3] == 0) && (w[5] == 0) && (w[7] == 0);
        int even_nonzero = (w[2] != 0) || (w[4] != 0) || (w[6] != 0);
        is64 = (odd_zero && even_nonzero) ? 1 : 0;
    }
    g_pos_is64 = is64;
}

// ---------------------------------------------------------------------------
// SGEMM (verified): C[M,N] = A[M,K] @ B[K,N], row-major.
// ---------------------------------------------------------------------------
__global__ __launch_bounds__(256) void sgemm_kernel(
    const float* A_fix, int a_sel, int b_sel,
    float* __restrict__ C, int M, int N, int K)
{
    const float* __restrict__ A  = (a_sel >= 0) ? (const float*)g_ptrs[a_sel] : A_fix;
    const float* __restrict__ Bm = (const float*)g_ptrs[b_sel];

    __shared__ float As[8][132];
    __shared__ float Bs[8][128];

    const int tid = threadIdx.x;
    const int tx = tid & 15;
    const int ty = tid >> 4;
    const int m0 = blockIdx.y * 128;
    const int n0 = blockIdx.x * 128;

    float acc[8][8];
#pragma unroll
    for (int i = 0; i < 8; i++)
#pragma unroll
        for (int j = 0; j < 8; j++) acc[i][j] = 0.f;

    const int arow = tid >> 1;
    const int acol = (tid & 1) * 4;
    const int brow = tid >> 5;
    const int bcol = (tid & 31) * 4;

    const float* Ap = A + (size_t)(m0 + arow) * K + acol;
    const float* Bp = Bm + (size_t)brow * N + n0 + bcol;

    for (int k0 = 0; k0 < K; k0 += 8) {
        float4 av = *(const float4*)(Ap + k0);
        float4 bv = *(const float4*)(Bp + (size_t)k0 * N);
        As[acol + 0][arow] = av.x;
        As[acol + 1][arow] = av.y;
        As[acol + 2][arow] = av.z;
        As[acol + 3][arow] = av.w;
        *(float4*)&Bs[brow][bcol] = bv;
        __syncthreads();
#pragma unroll
        for (int kk = 0; kk < 8; kk++) {
            float a[8], b[8];
            *(float4*)&a[0] = *(const float4*)&As[kk][ty * 8];
            *(float4*)&a[4] = *(const float4*)&As[kk][ty * 8 + 4];
            *(float4*)&b[0] = *(const float4*)&Bs[kk][tx * 8];
            *(float4*)&b[4] = *(const float4*)&Bs[kk][tx * 8 + 4];
#pragma unroll
            for (int i = 0; i < 8; i++)
#pragma unroll
                for (int j = 0; j < 8; j++)
                    acc[i][j] += a[i] * b[j];
        }
        __syncthreads();
    }

#pragma unroll
    for (int i = 0; i < 8; i++) {
        float* Cp = C + (size_t)(m0 + ty * 8 + i) * N + n0 + tx * 8;
        *(float4*)Cp       = make_float4(acc[i][0], acc[i][1], acc[i][2], acc[i][3]);
        *(float4*)(Cp + 4) = make_float4(acc[i][4], acc[i][5], acc[i][6], acc[i][7]);
    }
}

// ---------------------------------------------------------------------------
// RoPE in-place, ROTATION DIRECTION REVERSED (sin negated), theta = 10000.
// out[i]    = x[i]*cos + x[i+64]*sin
// out[i+64] = x[i+64]*cos - x[i]*sin
// ---------------------------------------------------------------------------
__global__ __launch_bounds__(256) void rope_kernel()
{
    int idx = blockIdx.x * blockDim.x + threadIdx.x;
    int i = idx & 63;
    int t = idx >> 6;
    int head = t % 40;
    int row = t / 40;
    if (row >= MROWS) return;

    const int* ids = (const int*)g_ptrs[5];
    int pos;
    if (ids) pos = ids[g_pos_is64 ? (row << 1) : row];
    else     pos = row & (SEQ - 1);

    float invf = expf(-ROPE_LN_OVER_HALF * (float)i);   // 10000^(-i/64)
    float ang = (float)pos * invf;
    float c, s;
    sincosf(ang, &c, &s);

    float* base;
    if (head < NHEADS) base = g_Q + (size_t)row * HID + head * HD;
    else               base = g_K + (size_t)row * KVD + (head - NHEADS) * HD;

    float x1 = base[i];
    float x2 = base[i + 64];
    base[i]      = x1 * c + x2 * s;   // reversed rotation
    base[i + 64] = x2 * c - x1 * s;
}

// ---------------------------------------------------------------------------
// Causal attention (verified): warp per query row, online softmax.
// ---------------------------------------------------------------------------
__global__ __launch_bounds__(512) void attn_naive_kernel()
{
    __shared__ float Ks[32 * 128];
    __shared__ float Vs[32 * 128];

    const int qt = blockIdx.x;
    const int bh = blockIdx.y;
    const int b = bh >> 5, h = bh & 31, kvh = h >> 2;
    const int w = threadIdx.x >> 5;
    const int lane = threadIdx.x & 31;
    const int q = qt * 16 + w;

    const float* Qg = g_Q + (size_t)(b * SEQ + q) * HID + h * HD;
    const float* Kg = g_K + (size_t)(b * SEQ) * KVD + kvh * HD;
    const float* Vg = g_V + (size_t)(b * SEQ) * KVD + kvh * HD;

    const float4 qv = *(const float4*)(Qg + lane * 4);
    float m = -CUDART_INF_F, l = 0.f;
    float ox = 0.f, oy = 0.f, oz = 0.f, ow = 0.f;
    const float scale = 0.08838834764831845f;   // 1/sqrt(128)

    const int ntiles = (qt * 16 + 15) / 32 + 1;

    for (int kt = 0; kt < ntiles; kt++) {
        __syncthreads();
        for (int v = threadIdx.x; v < 32 * 32; v += 512) {
            int r = v >> 5, c4 = (v & 31) * 4;
            *(float4*)&Ks[r * 128 + c4] = *(const float4*)(Kg + (size_t)(kt * 32 + r) * KVD + c4);
            *(float4*)&Vs[r * 128 + c4] = *(const float4*)(Vg + (size_t)(kt * 32 + r) * KVD + c4);
        }
        __syncthreads();

        const int klim = min(31, q - kt * 32);
        for (int k = 0; k <= klim; k++) {
            float4 kv = *(const float4*)&Ks[k * 128 + lane * 4];
            float d = qv.x * kv.x + qv.y * kv.y + qv.z * kv.z + qv.w * kv.w;
            d += __shfl_xor_sync(0xffffffffu, d, 16);
            d += __shfl_xor_sync(0xffffffffu, d, 8);
            d += __shfl_xor_sync(0xffffffffu, d, 4);
            d += __shfl_xor_sync(0xffffffffu, d, 2);
            d += __shfl_xor_sync(0xffffffffu, d, 1);
            float s = d * scale;
            float mnew = fmaxf(m, s);
            float alpha = __expf(m - mnew);
            float p = __expf(s - mnew);
            l = l * alpha + p;
            float4 vv = *(const float4*)&Vs[k * 128 + lane * 4];
            ox = ox * alpha + p * vv.x;
            oy = oy * alpha + p * vv.y;
            oz = oz * alpha + p * vv.z;
            ow = ow * alpha + p * vv.w;
            m = mnew;
        }
    }

    float inv = 1.f / l;
    float* Og = g_O + (size_t)(b * SEQ + q) * HID + h * HD + lane * 4;
    *(float4*)Og = make_float4(ox * inv, oy * inv, oz * inv, ow * inv);
}

// ---------------------------------------------------------------------------
extern "C" void kernel_launch(void* const* d_in, const int* in_sizes, int n_in,
                              void* d_out, int out_size)
{
    InArgs a;
    a.n = (n_in < 8) ? n_in : 8;
    for (int i = 0; i < 8; i++) {
        a.p[i]  = (i < n_in) ? (const float*)d_in[i] : nullptr;
        a.sz[i] = (i < n_in) ? in_sizes[i] : 0;
    }
    float* out = (float*)d_out;

    float *Q, *K, *V, *O;
    cudaGetSymbolAddress((void**)&Q, g_Q);
    cudaGetSymbolAddress((void**)&K, g_K);
    cudaGetSymbolAddress((void**)&V, g_V);
    cudaGetSymbolAddress((void**)&O, g_O);

    classify_kernel<<<1, 32>>>(a);

    sgemm_kernel<<<dim3(HID / 128, MROWS / 128), 256>>>(nullptr, 0, 1, Q, MROWS, HID, HID);
    sgemm_kernel<<<dim3(KVD / 128, MROWS / 128), 256>>>(nullptr, 0, 2, K, MROWS, KVD, HID);
    sgemm_kernel<<<dim3(KVD / 128, MROWS / 128), 256>>>(nullptr, 0, 3, V, MROWS, KVD, HID);

    rope_kernel<<<(MROWS * 40 * 64) / 256, 256>>>();

    attn_naive_kernel<<<dim3(SEQ / 16, BATCH * NHEADS), 512>>>();

    sgemm_kernel<<<dim3(HID / 128, MROWS / 128), 256>>>(O, -1, 4, out, MROWS, HID, HID);
}

// round 15
// speedup vs baseline: 1.1712x; 1.1712x over previous
#include <cuda_runtime.h>
#include <math.h>
#include <math_constants.h>

#define SEQ    2048
#define BATCH  2
#define HID    4096
#define NHEADS 32
#define NKV    8
#define HD     128
#define KVD    1024
#define MROWS  (BATCH*SEQ)
#define BIGSZ  16777216
#define MIDSZ  4194304
#define POSSZ  (BATCH*SEQ)

// ln(10000)/64
#define ROPE_LN_OVER_HALF 0.14391156831212787f

__device__ float g_Q[MROWS * HID];
__device__ float g_K[MROWS * KVD];
__device__ float g_V[MROWS * KVD];
__device__ float g_O[MROWS * HID];

// [0]=X, [1]=Wq, [2]=Wk, [3]=Wv, [4]=Wo, [5]=position_ids(raw)
__device__ unsigned long long g_ptrs[6];
__device__ int g_pos_is64;

struct InArgs {
    const float* p[8];
    int sz[8];
    int n;
};

__global__ void classify_kernel(InArgs a)
{
    if (threadIdx.x != 0 || blockIdx.x != 0) return;

    int bigs[3]; int nb = 0;
    int mids[2]; int nm = 0;
    int ipos = -1;
    for (int i = 0; i < a.n && i < 8; i++) {
        if (a.sz[i] == BIGSZ && nb < 3) bigs[nb++] = i;
        else if (a.sz[i] == MIDSZ && nm < 2) mids[nm++] = i;
        else if (a.sz[i] == POSSZ && ipos < 0) ipos = i;
    }

    int iX, iWq, iWk, iWv, iWo;
    if (nb == 3 && nm == 2) {
        float avg[3];
        for (int t = 0; t < 3; t++) {
            const float* p = a.p[bigs[t]];
            float s = 0.f;
            for (int j = 0; j < 512; j++) s += fabsf(p[j * 97]);
            avg[t] = s * (1.f / 512.f);
        }
        int hid = 0;
        if (avg[1] > avg[hid]) hid = 1;
        if (avg[2] > avg[hid]) hid = 2;
        int rem[2], c = 0;
        for (int t = 0; t < 3; t++) if (t != hid) rem[c++] = t;
        iX = bigs[hid];
        if (hid == 2) { iWq = bigs[rem[1]]; iWo = bigs[rem[0]]; }
        else          { iWq = bigs[rem[0]]; iWo = bigs[rem[1]]; }
        iWk = mids[0];
        iWv = mids[1];
    } else {
        iX = 0; iWq = 2; iWk = 3; iWv = 4; iWo = 5;
    }

    g_ptrs[0] = (unsigned long long)a.p[iX];
    g_ptrs[1] = (unsigned long long)a.p[iWq];
    g_ptrs[2] = (unsigned long long)a.p[iWk];
    g_ptrs[3] = (unsigned long long)a.p[iWv];
    g_ptrs[4] = (unsigned long long)a.p[iWo];
    g_ptrs[5] = (ipos >= 0) ? (unsigned long long)a.p[ipos] : 0ull;

    int is64 = 0;
    if (ipos >= 0) {
        const int* w = (const int*)a.p[ipos];
        int odd_zero = (w[1] == 0) && (w[3] == 0) && (w[5] == 0) && (w[7] == 0);
        int even_nonzero = (w[2] != 0) || (w[4] != 0) || (w[6] != 0);
        is64 = (odd_zero && even_nonzero) ? 1 : 0;
    }
    g_pos_is64 = is64;
}

// ---------------------------------------------------------------------------
// SGEMM (verified): C[M,N] = A[M,K] @ B[K,N], row-major.
// ---------------------------------------------------------------------------
__global__ __launch_bounds__(256) void sgemm_kernel(
    const float* A_fix, int a_sel, int b_sel,
    float* __restrict__ C, int M, int N, int K)
{
    const float* __restrict__ A  = (a_sel >= 0) ? (const float*)g_ptrs[a_sel] : A_fix;
    const float* __restrict__ Bm = (const float*)g_ptrs[b_sel];

    __shared__ float As[8][132];
    __shared__ float Bs[8][128];

    const int tid = threadIdx.x;
    const int tx = tid & 15;
    const int ty = tid >> 4;
    const int m0 = blockIdx.y * 128;
    const int n0 = blockIdx.x * 128;

    float acc[8][8];
#pragma unroll
    for (int i = 0; i < 8; i++)
#pragma unroll
        for (int j = 0; j < 8; j++) acc[i][j] = 0.f;

    const int arow = tid >> 1;
    const int acol = (tid & 1) * 4;
    const int brow = tid >> 5;
    const int bcol = (tid & 31) * 4;

    const float* Ap = A + (size_t)(m0 + arow) * K + acol;
    const float* Bp = Bm + (size_t)brow * N + n0 + bcol;

    for (int k0 = 0; k0 < K; k0 += 8) {
        float4 av = *(const float4*)(Ap + k0);
        float4 bv = *(const float4*)(Bp + (size_t)k0 * N);
        As[acol + 0][arow] = av.x;
        As[acol + 1][arow] = av.y;
        As[acol + 2][arow] = av.z;
        As[acol + 3][arow] = av.w;
        *(float4*)&Bs[brow][bcol] = bv;
        __syncthreads();
#pragma unroll
        for (int kk = 0; kk < 8; kk++) {
            float a[8], b[8];
            *(float4*)&a[0] = *(const float4*)&As[kk][ty * 8];
            *(float4*)&a[4] = *(const float4*)&As[kk][ty * 8 + 4];
            *(float4*)&b[0] = *(const float4*)&Bs[kk][tx * 8];
            *(float4*)&b[4] = *(const float4*)&Bs[kk][tx * 8 + 4];
#pragma unroll
            for (int i = 0; i < 8; i++)
#pragma unroll
                for (int j = 0; j < 8; j++)
                    acc[i][j] += a[i] * b[j];
        }
        __syncthreads();
    }

#pragma unroll
    for (int i = 0; i < 8; i++) {
        float* Cp = C + (size_t)(m0 + ty * 8 + i) * N + n0 + tx * 8;
        *(float4*)Cp       = make_float4(acc[i][0], acc[i][1], acc[i][2], acc[i][3]);
        *(float4*)(Cp + 4) = make_float4(acc[i][4], acc[i][5], acc[i][6], acc[i][7]);
    }
}

// ---------------------------------------------------------------------------
// RoPE in-place, REVERSED rotation (verified), theta = 10000.
// out[i] = x[i]*cos + x[i+64]*sin ; out[i+64] = x[i+64]*cos - x[i]*sin
// ---------------------------------------------------------------------------
__global__ __launch_bounds__(256) void rope_kernel()
{
    int idx = blockIdx.x * blockDim.x + threadIdx.x;
    int i = idx & 63;
    int t = idx >> 6;
    int head = t % 40;
    int row = t / 40;
    if (row >= MROWS) return;

    const int* ids = (const int*)g_ptrs[5];
    int pos;
    if (ids) pos = ids[g_pos_is64 ? (row << 1) : row];
    else     pos = row & (SEQ - 1);

    float invf = expf(-ROPE_LN_OVER_HALF * (float)i);
    float ang = (float)pos * invf;
    float c, s;
    sincosf(ang, &c, &s);

    float* base;
    if (head < NHEADS) base = g_Q + (size_t)row * HID + head * HD;
    else               base = g_K + (size_t)row * KVD + (head - NHEADS) * HD;

    float x1 = base[i];
    float x2 = base[i + 64];
    base[i]      = x1 * c + x2 * s;   // reversed rotation (verified)
    base[i + 64] = x2 * c - x1 * s;
}

// ---------------------------------------------------------------------------
// Tiled flash attention (functionally equivalent to verified naive kernel).
// BM=32 queries/CTA, BN=64 keys/tile, d=128, 128 threads.
//   row = tid/4, part = tid%4; score: 16 cols/thread (c = part+4j);
//   softmax: shfl over the 4 lanes of a row; PV: 32 dims/thread.
// grid: (SEQ/32, BATCH*NHEADS)
// ---------------------------------------------------------------------------
__global__ __launch_bounds__(128) void flash_kernel()
{
    extern __shared__ float sm[];
    float* Qs = sm;                      // [32][132]
    float* Ks = Qs + 32 * 132;           // [64][132]
    float* Vs = Ks + 64 * 132;           // [64][128]
    float* Ps = Vs + 64 * 128;           // [32][68]

    const int qt = blockIdx.x;
    const int bh = blockIdx.y;
    const int b = bh >> 5, h = bh & 31, kvh = h >> 2;
    const int tid = threadIdx.x;
    const int row = tid >> 2, part = tid & 3;

    const float* Qg = g_Q + (size_t)(b * SEQ + qt * 32) * HID + h * HD;
    const float* Kg = g_K + (size_t)(b * SEQ) * KVD + kvh * HD;
    const float* Vg = g_V + (size_t)(b * SEQ) * KVD + kvh * HD;

    for (int v = tid; v < 32 * 32; v += 128) {
        int r = v >> 5, c4 = (v & 31) << 2;
        *(float4*)&Qs[r * 132 + c4] = *(const float4*)(Qg + (size_t)r * HID + c4);
    }

    float m = -CUDART_INF_F, l = 0.f;
    float o[32];
#pragma unroll
    for (int d = 0; d < 32; d++) o[d] = 0.f;

    const int qg = qt * 32 + row;
    const int ntiles = (qt * 32 + 31) / 64 + 1;
    const float scale = 0.08838834764831845f;

    for (int kt = 0; kt < ntiles; kt++) {
        __syncthreads();
        for (int v = tid; v < 64 * 32; v += 128) {
            int r = v >> 5, c4 = (v & 31) << 2;
            *(float4*)&Ks[r * 132 + c4] = *(const float4*)(Kg + (size_t)(kt * 64 + r) * KVD + c4);
            *(float4*)&Vs[r * 128 + c4] = *(const float4*)(Vg + (size_t)(kt * 64 + r) * KVD + c4);
        }
        __syncthreads();

        float sc[16];
#pragma unroll
        for (int j = 0; j < 16; j++) sc[j] = 0.f;
#pragma unroll 4
        for (int k4 = 0; k4 < 128; k4 += 4) {
            float4 qv = *(const float4*)&Qs[row * 132 + k4];
#pragma unroll
            for (int j = 0; j < 16; j++) {
                const int c = part + (j << 2);
                float4 kv = *(const float4*)&Ks[c * 132 + k4];
                sc[j] += qv.x * kv.x + qv.y * kv.y + qv.z * kv.z + qv.w * kv.w;
            }
        }

        const bool full = (kt * 64 + 63) <= (qt * 32);
        float mt = -CUDART_INF_F;
#pragma unroll
        for (int j = 0; j < 16; j++) {
            int cg = kt * 64 + part + (j << 2);
            sc[j] = (full || cg <= qg) ? sc[j] * scale : -CUDART_INF_F;
            mt = fmaxf(mt, sc[j]);
        }
        mt = fmaxf(mt, __shfl_xor_sync(0xffffffffu, mt, 1));
        mt = fmaxf(mt, __shfl_xor_sync(0xffffffffu, mt, 2));
        float mnew = fmaxf(m, mt);
        float alpha = __expf(m - mnew);

        float ps = 0.f;
#pragma unroll
        for (int j = 0; j < 16; j++) {
            float p = __expf(sc[j] - mnew);
            ps += p;
            Ps[row * 68 + part + (j << 2)] = p;
        }
        ps += __shfl_xor_sync(0xffffffffu, ps, 1);
        ps += __shfl_xor_sync(0xffffffffu, ps, 2);
        l = l * alpha + ps;
        m = mnew;
#pragma unroll
        for (int d = 0; d < 32; d++) o[d] *= alpha;

        __syncthreads();

#pragma unroll 4
        for (int c = 0; c < 64; c++) {
            float p = Ps[row * 68 + c];
            const float* vr = &Vs[c * 128 + part * 4];
#pragma unroll
            for (int j = 0; j < 8; j++) {
                float4 vv = *(const float4*)(vr + j * 16);
                o[j * 4 + 0] += p * vv.x;
                o[j * 4 + 1] += p * vv.y;
                o[j * 4 + 2] += p * vv.z;
                o[j * 4 + 3] += p * vv.w;
            }
        }
    }

    float inv = 1.f / l;
    float* Og = g_O + (size_t)(b * SEQ + qg) * HID + h * HD + part * 4;
#pragma unroll
    for (int j = 0; j < 8; j++) {
        float4 vv = make_float4(o[j * 4 + 0] * inv, o[j * 4 + 1] * inv,
                                o[j * 4 + 2] * inv, o[j * 4 + 3] * inv);
        *(float4*)(Og + j * 16) = vv;
    }
}

// ---------------------------------------------------------------------------
extern "C" void kernel_launch(void* const* d_in, const int* in_sizes, int n_in,
                              void* d_out, int out_size)
{
    InArgs a;
    a.n = (n_in < 8) ? n_in : 8;
    for (int i = 0; i < 8; i++) {
        a.p[i]  = (i < n_in) ? (const float*)d_in[i] : nullptr;
        a.sz[i] = (i < n_in) ? in_sizes[i] : 0;
    }
    float* out = (float*)d_out;

    float *Q, *K, *V, *O;
    cudaGetSymbolAddress((void**)&Q, g_Q);
    cudaGetSymbolAddress((void**)&K, g_K);
    cudaGetSymbolAddress((void**)&V, g_V);
    cudaGetSymbolAddress((void**)&O, g_O);

    classify_kernel<<<1, 32>>>(a);

    sgemm_kernel<<<dim3(HID / 128, MROWS / 128), 256>>>(nullptr, 0, 1, Q, MROWS, HID, HID);
    sgemm_kernel<<<dim3(KVD / 128, MROWS / 128), 256>>>(nullptr, 0, 2, K, MROWS, KVD, HID);
    sgemm_kernel<<<dim3(KVD / 128, MROWS / 128), 256>>>(nullptr, 0, 3, V, MROWS, KVD, HID);

    rope_kernel<<<(MROWS * 40 * 64) / 256, 256>>>();

    constexpr int SMEM = (32 * 132 + 64 * 132 + 64 * 128 + 32 * 68) * 4;  // 92160
    cudaFuncSetAttribute(flash_kernel, cudaFuncAttributeMaxDynamicSharedMemorySize, SMEM);
    flash_kernel<<<dim3(SEQ / 32, BATCH * NHEADS), 128, SMEM>>>();

    sgemm_kernel<<<dim3(HID / 128, MROWS / 128), 256>>>(O, -1, 4, out, MROWS, HID, HID);
}

// round 16
// speedup vs baseline: 1.8419x; 1.5727x over previous
#include <cuda_runtime.h>
#include <math.h>
#include <math_constants.h>

#define SEQ    2048
#define BATCH  2
#define HID    4096
#define NHEADS 32
#define NKV    8
#define HD     128
#define KVD    1024
#define MROWS  (BATCH*SEQ)
#define BIGSZ  16777216
#define MIDSZ  4194304
#define POSSZ  (BATCH*SEQ)

// ln(10000)/64
#define ROPE_LN_OVER_HALF 0.14391156831212787f

__device__ float g_Q[MROWS * HID];
__device__ float g_K[MROWS * KVD];
__device__ float g_V[MROWS * KVD];
__device__ float g_O[MROWS * HID];

// [0]=X, [1]=Wq, [2]=Wk, [3]=Wv, [4]=Wo, [5]=position_ids(raw)
__device__ unsigned long long g_ptrs[6];
__device__ int g_pos_is64;

struct InArgs {
    const float* p[8];
    int sz[8];
    int n;
};

__global__ void classify_kernel(InArgs a)
{
    if (threadIdx.x != 0 || blockIdx.x != 0) return;

    int bigs[3]; int nb = 0;
    int mids[2]; int nm = 0;
    int ipos = -1;
    for (int i = 0; i < a.n && i < 8; i++) {
        if (a.sz[i] == BIGSZ && nb < 3) bigs[nb++] = i;
        else if (a.sz[i] == MIDSZ && nm < 2) mids[nm++] = i;
        else if (a.sz[i] == POSSZ && ipos < 0) ipos = i;
    }

    int iX, iWq, iWk, iWv, iWo;
    if (nb == 3 && nm == 2) {
        float avg[3];
        for (int t = 0; t < 3; t++) {
            const float* p = a.p[bigs[t]];
            float s = 0.f;
            for (int j = 0; j < 512; j++) s += fabsf(p[j * 97]);
            avg[t] = s * (1.f / 512.f);
        }
        int hid = 0;
        if (avg[1] > avg[hid]) hid = 1;
        if (avg[2] > avg[hid]) hid = 2;
        int rem[2], c = 0;
        for (int t = 0; t < 3; t++) if (t != hid) rem[c++] = t;
        iX = bigs[hid];
        if (hid == 2) { iWq = bigs[rem[1]]; iWo = bigs[rem[0]]; }
        else          { iWq = bigs[rem[0]]; iWo = bigs[rem[1]]; }
        iWk = mids[0];
        iWv = mids[1];
    } else {
        iX = 0; iWq = 2; iWk = 3; iWv = 4; iWo = 5;
    }

    g_ptrs[0] = (unsigned long long)a.p[iX];
    g_ptrs[1] = (unsigned long long)a.p[iWq];
    g_ptrs[2] = (unsigned long long)a.p[iWk];
    g_ptrs[3] = (unsigned long long)a.p[iWv];
    g_ptrs[4] = (unsigned long long)a.p[iWo];
    g_ptrs[5] = (ipos >= 0) ? (unsigned long long)a.p[ipos] : 0ull;

    int is64 = 0;
    if (ipos >= 0) {
        const int* w = (const int*)a.p[ipos];
        int odd_zero = (w[1] == 0) && (w[3] == 0) && (w[5] == 0) && (w[7] == 0);
        int even_nonzero = (w[2] != 0) || (w[4] != 0) || (w[6] != 0);
        is64 = (odd_zero && even_nonzero) ? 1 : 0;
    }
    g_pos_is64 = is64;
}

// ---------------------------------------------------------------------------
// Tensor-core GEMM via mma.sync m16n8k8 tf32.
// C[M,N] = A[M,K] @ B[K,N], row-major. CTA tile 128x128, k-chunk 32.
// 8 warps: warp (wid&3) -> m offset, (wid>>2) -> n offset; warp tile 32x64.
// ---------------------------------------------------------------------------
__device__ __forceinline__ unsigned f2tf32(float x)
{
    unsigned r;
    asm("cvt.rna.tf32.f32 %0, %1;" : "=r"(r) : "f"(x));
    return r;
}

__device__ __forceinline__ void mma_tf32(float* c, const unsigned* a, const unsigned* b)
{
    asm volatile(
        "mma.sync.aligned.m16n8k8.row.col.f32.tf32.tf32.f32 "
        "{%0,%1,%2,%3}, {%4,%5,%6,%7}, {%8,%9}, {%0,%1,%2,%3};"
        : "+f"(c[0]), "+f"(c[1]), "+f"(c[2]), "+f"(c[3])
        : "r"(a[0]), "r"(a[1]), "r"(a[2]), "r"(a[3]), "r"(b[0]), "r"(b[1]));
}

__global__ __launch_bounds__(256) void tc_gemm_kernel(
    const float* A_fix, int a_sel, int b_sel,
    float* __restrict__ C, int M, int N, int K)
{
    const float* __restrict__ A  = (a_sel >= 0) ? (const float*)g_ptrs[a_sel] : A_fix;
    const float* __restrict__ Bm = (const float*)g_ptrs[b_sel];

    __shared__ unsigned As[128][36];   // [m][k] tf32 bits, pad 4 -> frag reads conflict-free
    __shared__ unsigned Bs[32][136];   // [k][n] tf32 bits, pad 8 -> frag reads conflict-free

    const int tid  = threadIdx.x;
    const int lane = tid & 31;
    const int wid  = tid >> 5;
    const int wm   = (wid & 3) * 32;   // warp m offset in tile
    const int wn   = (wid >> 2) * 64;  // warp n offset in tile
    const int g    = lane >> 2;        // group id 0..7
    const int tg   = lane & 3;         // thread-in-group 0..3

    const int m0 = blockIdx.y * 128;
    const int n0 = blockIdx.x * 128;

    float c[2][8][4];
#pragma unroll
    for (int mi = 0; mi < 2; mi++)
#pragma unroll
        for (int nj = 0; nj < 8; nj++)
#pragma unroll
            for (int e = 0; e < 4; e++) c[mi][nj][e] = 0.f;

    const int arow = tid >> 1;            // 0..127
    const int acol = (tid & 1) * 16;      // 0 or 16
    const int brow = tid & 31;            // 0..31
    const int bcol = (tid >> 5) * 16;     // 0..112

    const float* Ap = A + (size_t)(m0 + arow) * K + acol;

    for (int k0 = 0; k0 < K; k0 += 32) {
        // A chunk: 128 x 32
#pragma unroll
        for (int i = 0; i < 4; i++) {
            float4 v = *(const float4*)(Ap + k0 + i * 4);
            As[arow][acol + i * 4 + 0] = f2tf32(v.x);
            As[arow][acol + i * 4 + 1] = f2tf32(v.y);
            As[arow][acol + i * 4 + 2] = f2tf32(v.z);
            As[arow][acol + i * 4 + 3] = f2tf32(v.w);
        }
        // B chunk: 32 x 128
        const float* Bp = Bm + (size_t)(k0 + brow) * N + n0 + bcol;
#pragma unroll
        for (int i = 0; i < 4; i++) {
            float4 v = *(const float4*)(Bp + i * 4);
            Bs[brow][bcol + i * 4 + 0] = f2tf32(v.x);
            Bs[brow][bcol + i * 4 + 1] = f2tf32(v.y);
            Bs[brow][bcol + i * 4 + 2] = f2tf32(v.z);
            Bs[brow][bcol + i * 4 + 3] = f2tf32(v.w);
        }
        __syncthreads();

#pragma unroll
        for (int ks = 0; ks < 32; ks += 8) {
            unsigned a[2][4], b[8][2];
#pragma unroll
            for (int mi = 0; mi < 2; mi++) {
                a[mi][0] = As[wm + mi * 16 + g][ks + tg];
                a[mi][1] = As[wm + mi * 16 + 8 + g][ks + tg];
                a[mi][2] = As[wm + mi * 16 + g][ks + 4 + tg];
                a[mi][3] = As[wm + mi * 16 + 8 + g][ks + 4 + tg];
            }
#pragma unroll
            for (int nj = 0; nj < 8; nj++) {
                b[nj][0] = Bs[ks + tg][wn + nj * 8 + g];
                b[nj][1] = Bs[ks + 4 + tg][wn + nj * 8 + g];
            }
#pragma unroll
            for (int mi = 0; mi < 2; mi++)
#pragma unroll
                for (int nj = 0; nj < 8; nj++)
                    mma_tf32(c[mi][nj], a[mi], b[nj]);
        }
        __syncthreads();
    }

    // Epilogue: c0,c1 -> (row, 2tg..2tg+1); c2,c3 -> (row+8, same)
#pragma unroll
    for (int mi = 0; mi < 2; mi++) {
#pragma unroll
        for (int nj = 0; nj < 8; nj++) {
            float* Cp = C + (size_t)(m0 + wm + mi * 16 + g) * N
                          + n0 + wn + nj * 8 + 2 * tg;
            *(float2*)Cp           = make_float2(c[mi][nj][0], c[mi][nj][1]);
            *(float2*)(Cp + 8 * N) = make_float2(c[mi][nj][2], c[mi][nj][3]);
        }
    }
}

// ---------------------------------------------------------------------------
// RoPE in-place, REVERSED rotation (verified), theta = 10000.
// ---------------------------------------------------------------------------
__global__ __launch_bounds__(256) void rope_kernel()
{
    int idx = blockIdx.x * blockDim.x + threadIdx.x;
    int i = idx & 63;
    int t = idx >> 6;
    int head = t % 40;
    int row = t / 40;
    if (row >= MROWS) return;

    const int* ids = (const int*)g_ptrs[5];
    int pos;
    if (ids) pos = ids[g_pos_is64 ? (row << 1) : row];
    else     pos = row & (SEQ - 1);

    float invf = expf(-ROPE_LN_OVER_HALF * (float)i);
    float ang = (float)pos * invf;
    float c, s;
    sincosf(ang, &c, &s);

    float* base;
    if (head < NHEADS) base = g_Q + (size_t)row * HID + head * HD;
    else               base = g_K + (size_t)row * KVD + (head - NHEADS) * HD;

    float x1 = base[i];
    float x2 = base[i + 64];
    base[i]      = x1 * c + x2 * s;   // reversed rotation (verified)
    base[i + 64] = x2 * c - x1 * s;
}

// ---------------------------------------------------------------------------
// Tiled flash attention (verified). BM=32, BN=64, d=128, 128 threads.
// ---------------------------------------------------------------------------
__global__ __launch_bounds__(128) void flash_kernel()
{
    extern __shared__ float sm[];
    float* Qs = sm;                      // [32][132]
    float* Ks = Qs + 32 * 132;           // [64][132]
    float* Vs = Ks + 64 * 132;           // [64][128]
    float* Ps = Vs + 64 * 128;           // [32][68]

    const int qt = blockIdx.x;
    const int bh = blockIdx.y;
    const int b = bh >> 5, h = bh & 31, kvh = h >> 2;
    const int tid = threadIdx.x;
    const int row = tid >> 2, part = tid & 3;

    const float* Qg = g_Q + (size_t)(b * SEQ + qt * 32) * HID + h * HD;
    const float* Kg = g_K + (size_t)(b * SEQ) * KVD + kvh * HD;
    const float* Vg = g_V + (size_t)(b * SEQ) * KVD + kvh * HD;

    for (int v = tid; v < 32 * 32; v += 128) {
        int r = v >> 5, c4 = (v & 31) << 2;
        *(float4*)&Qs[r * 132 + c4] = *(const float4*)(Qg + (size_t)r * HID + c4);
    }

    float m = -CUDART_INF_F, l = 0.f;
    float o[32];
#pragma unroll
    for (int d = 0; d < 32; d++) o[d] = 0.f;

    const int qg = qt * 32 + row;
    const int ntiles = (qt * 32 + 31) / 64 + 1;
    const float scale = 0.08838834764831845f;

    for (int kt = 0; kt < ntiles; kt++) {
        __syncthreads();
        for (int v = tid; v < 64 * 32; v += 128) {
            int r = v >> 5, c4 = (v & 31) << 2;
            *(float4*)&Ks[r * 132 + c4] = *(const float4*)(Kg + (size_t)(kt * 64 + r) * KVD + c4);
            *(float4*)&Vs[r * 128 + c4] = *(const float4*)(Vg + (size_t)(kt * 64 + r) * KVD + c4);
        }
        __syncthreads();

        float sc[16];
#pragma unroll
        for (int j = 0; j < 16; j++) sc[j] = 0.f;
#pragma unroll 4
        for (int k4 = 0; k4 < 128; k4 += 4) {
            float4 qv = *(const float4*)&Qs[row * 132 + k4];
#pragma unroll
            for (int j = 0; j < 16; j++) {
                const int c = part + (j << 2);
                float4 kv = *(const float4*)&Ks[c * 132 + k4];
                sc[j] += qv.x * kv.x + qv.y * kv.y + qv.z * kv.z + qv.w * kv.w;
            }
        }

        const bool full = (kt * 64 + 63) <= (qt * 32);
        float mt = -CUDART_INF_F;
#pragma unroll
        for (int j = 0; j < 16; j++) {
            int cg = kt * 64 + part + (j << 2);
            sc[j] = (full || cg <= qg) ? sc[j] * scale : -CUDART_INF_F;
            mt = fmaxf(mt, sc[j]);
        }
        mt = fmaxf(mt, __shfl_xor_sync(0xffffffffu, mt, 1));
        mt = fmaxf(mt, __shfl_xor_sync(0xffffffffu, mt, 2));
        float mnew = fmaxf(m, mt);
        float alpha = __expf(m - mnew);

        float ps = 0.f;
#pragma unroll
        for (int j = 0; j < 16; j++) {
            float p = __expf(sc[j] - mnew);
            ps += p;
            Ps[row * 68 + part + (j << 2)] = p;
        }
        ps += __shfl_xor_sync(0xffffffffu, ps, 1);
        ps += __shfl_xor_sync(0xffffffffu, ps, 2);
        l = l * alpha + ps;
        m = mnew;
#pragma unroll
        for (int d = 0; d < 32; d++) o[d] *= alpha;

        __syncthreads();

#pragma unroll 4
        for (int c = 0; c < 64; c++) {
            float p = Ps[row * 68 + c];
            const float* vr = &Vs[c * 128 + part * 4];
#pragma unroll
            for (int j = 0; j < 8; j++) {
                float4 vv = *(const float4*)(vr + j * 16);
                o[j * 4 + 0] += p * vv.x;
                o[j * 4 + 1] += p * vv.y;
                o[j * 4 + 2] += p * vv.z;
                o[j * 4 + 3] += p * vv.w;
            }
        }
    }

    float inv = 1.f / l;
    float* Og = g_O + (size_t)(b * SEQ + qg) * HID + h * HD + part * 4;
#pragma unroll
    for (int j = 0; j < 8; j++) {
        float4 vv = make_float4(o[j * 4 + 0] * inv, o[j * 4 + 1] * inv,
                                o[j * 4 + 2] * inv, o[j * 4 + 3] * inv);
        *(float4*)(Og + j * 16) = vv;
    }
}

// ---------------------------------------------------------------------------
extern "C" void kernel_launch(void* const* d_in, const int* in_sizes, int n_in,
                              void* d_out, int out_size)
{
    InArgs a;
    a.n = (n_in < 8) ? n_in : 8;
    for (int i = 0; i < 8; i++) {
        a.p[i]  = (i < n_in) ? (const float*)d_in[i] : nullptr;
        a.sz[i] = (i < n_in) ? in_sizes[i] : 0;
    }
    float* out = (float*)d_out;

    float *Q, *K, *V, *O;
    cudaGetSymbolAddress((void**)&Q, g_Q);
    cudaGetSymbolAddress((void**)&K, g_K);
    cudaGetSymbolAddress((void**)&V, g_V);
    cudaGetSymbolAddress((void**)&O, g_O);

    classify_kernel<<<1, 32>>>(a);

    tc_gemm_kernel<<<dim3(HID / 128, MROWS / 128), 256>>>(nullptr, 0, 1, Q, MROWS, HID, HID);
    tc_gemm_kernel<<<dim3(KVD / 128, MROWS / 128), 256>>>(nullptr, 0, 2, K, MROWS, KVD, HID);
    tc_gemm_kernel<<<dim3(KVD / 128, MROWS / 128), 256>>>(nullptr, 0, 3, V, MROWS, KVD, HID);

    rope_kernel<<<(MROWS * 40 * 64) / 256, 256>>>();

    constexpr int SMEM = (32 * 132 + 64 * 132 + 64 * 128 + 32 * 68) * 4;  // 92160
    cudaFuncSetAttribute(flash_kernel, cudaFuncAttributeMaxDynamicSharedMemorySize, SMEM);
    flash_kernel<<<dim3(SEQ / 32, BATCH * NHEADS), 128, SMEM>>>();

    tc_gemm_kernel<<<dim3(HID / 128, MROWS / 128), 256>>>(O, -1, 4, out, MROWS, HID, HID);
}

// round 17
// speedup vs baseline: 2.6194x; 1.4221x over previous
#include <cuda_runtime.h>
#include <math.h>
#include <math_constants.h>

#define SEQ    2048
#define BATCH  2
#define HID    4096
#define NHEADS 32
#define NKV    8
#define HD     128
#define KVD    1024
#define MROWS  (BATCH*SEQ)
#define BIGSZ  16777216
#define MIDSZ  4194304
#define POSSZ  (BATCH*SEQ)

// ln(10000)/64
#define ROPE_LN_OVER_HALF 0.14391156831212787f

__device__ float g_Q[MROWS * HID];
__device__ float g_K[MROWS * KVD];
__device__ float g_V[MROWS * KVD];
__device__ float g_O[MROWS * HID];

// [0]=X, [1]=Wq, [2]=Wk, [3]=Wv, [4]=Wo, [5]=position_ids(raw)
__device__ unsigned long long g_ptrs[6];
__device__ int g_pos_is64;

struct InArgs {
    const float* p[8];
    int sz[8];
    int n;
};

__global__ void classify_kernel(InArgs a)
{
    if (threadIdx.x != 0 || blockIdx.x != 0) return;

    int bigs[3]; int nb = 0;
    int mids[2]; int nm = 0;
    int ipos = -1;
    for (int i = 0; i < a.n && i < 8; i++) {
        if (a.sz[i] == BIGSZ && nb < 3) bigs[nb++] = i;
        else if (a.sz[i] == MIDSZ && nm < 2) mids[nm++] = i;
        else if (a.sz[i] == POSSZ && ipos < 0) ipos = i;
    }

    int iX, iWq, iWk, iWv, iWo;
    if (nb == 3 && nm == 2) {
        float avg[3];
        for (int t = 0; t < 3; t++) {
            const float* p = a.p[bigs[t]];
            float s = 0.f;
            for (int j = 0; j < 512; j++) s += fabsf(p[j * 97]);
            avg[t] = s * (1.f / 512.f);
        }
        int hid = 0;
        if (avg[1] > avg[hid]) hid = 1;
        if (avg[2] > avg[hid]) hid = 2;
        int rem[2], c = 0;
        for (int t = 0; t < 3; t++) if (t != hid) rem[c++] = t;
        iX = bigs[hid];
        if (hid == 2) { iWq = bigs[rem[1]]; iWo = bigs[rem[0]]; }
        else          { iWq = bigs[rem[0]]; iWo = bigs[rem[1]]; }
        iWk = mids[0];
        iWv = mids[1];
    } else {
        iX = 0; iWq = 2; iWk = 3; iWv = 4; iWo = 5;
    }

    g_ptrs[0] = (unsigned long long)a.p[iX];
    g_ptrs[1] = (unsigned long long)a.p[iWq];
    g_ptrs[2] = (unsigned long long)a.p[iWk];
    g_ptrs[3] = (unsigned long long)a.p[iWv];
    g_ptrs[4] = (unsigned long long)a.p[iWo];
    g_ptrs[5] = (ipos >= 0) ? (unsigned long long)a.p[ipos] : 0ull;

    int is64 = 0;
    if (ipos >= 0) {
        const int* w = (const int*)a.p[ipos];
        int odd_zero = (w[1] == 0) && (w[3] == 0) && (w[5] == 0) && (w[7] == 0);
        int even_nonzero = (w[2] != 0) || (w[4] != 0) || (w[6] != 0);
        is64 = (odd_zero && even_nonzero) ? 1 : 0;
    }
    g_pos_is64 = is64;
}

// ---------------------------------------------------------------------------
__device__ __forceinline__ unsigned f2tf32(float x)
{
    unsigned r;
    asm("cvt.rna.tf32.f32 %0, %1;" : "=r"(r) : "f"(x));
    return r;
}

__device__ __forceinline__ void mma_tf32(float* c, const unsigned* a, const unsigned* b)
{
    asm volatile(
        "mma.sync.aligned.m16n8k8.row.col.f32.tf32.tf32.f32 "
        "{%0,%1,%2,%3}, {%4,%5,%6,%7}, {%8,%9}, {%0,%1,%2,%3};"
        : "+f"(c[0]), "+f"(c[1]), "+f"(c[2]), "+f"(c[3])
        : "r"(a[0]), "r"(a[1]), "r"(a[2]), "r"(a[3]), "r"(b[0]), "r"(b[1]));
}

// ---------------------------------------------------------------------------
// Tensor-core GEMM (verified R16): C[M,N] = A[M,K] @ B[K,N].
// ---------------------------------------------------------------------------
__global__ __launch_bounds__(256) void tc_gemm_kernel(
    const float* A_fix, int a_sel, int b_sel,
    float* __restrict__ C, int M, int N, int K)
{
    const float* __restrict__ A  = (a_sel >= 0) ? (const float*)g_ptrs[a_sel] : A_fix;
    const float* __restrict__ Bm = (const float*)g_ptrs[b_sel];

    __shared__ unsigned As[128][36];
    __shared__ unsigned Bs[32][136];

    const int tid  = threadIdx.x;
    const int lane = tid & 31;
    const int wid  = tid >> 5;
    const int wm   = (wid & 3) * 32;
    const int wn   = (wid >> 2) * 64;
    const int g    = lane >> 2;
    const int tg   = lane & 3;

    const int m0 = blockIdx.y * 128;
    const int n0 = blockIdx.x * 128;

    float c[2][8][4];
#pragma unroll
    for (int mi = 0; mi < 2; mi++)
#pragma unroll
        for (int nj = 0; nj < 8; nj++)
#pragma unroll
            for (int e = 0; e < 4; e++) c[mi][nj][e] = 0.f;

    const int arow = tid >> 1;
    const int acol = (tid & 1) * 16;
    const int brow = tid & 31;
    const int bcol = (tid >> 5) * 16;

    const float* Ap = A + (size_t)(m0 + arow) * K + acol;

    for (int k0 = 0; k0 < K; k0 += 32) {
#pragma unroll
        for (int i = 0; i < 4; i++) {
            float4 v = *(const float4*)(Ap + k0 + i * 4);
            As[arow][acol + i * 4 + 0] = f2tf32(v.x);
            As[arow][acol + i * 4 + 1] = f2tf32(v.y);
            As[arow][acol + i * 4 + 2] = f2tf32(v.z);
            As[arow][acol + i * 4 + 3] = f2tf32(v.w);
        }
        const float* Bp = Bm + (size_t)(k0 + brow) * N + n0 + bcol;
#pragma unroll
        for (int i = 0; i < 4; i++) {
            float4 v = *(const float4*)(Bp + i * 4);
            Bs[brow][bcol + i * 4 + 0] = f2tf32(v.x);
            Bs[brow][bcol + i * 4 + 1] = f2tf32(v.y);
            Bs[brow][bcol + i * 4 + 2] = f2tf32(v.z);
            Bs[brow][bcol + i * 4 + 3] = f2tf32(v.w);
        }
        __syncthreads();

#pragma unroll
        for (int ks = 0; ks < 32; ks += 8) {
            unsigned a[2][4], b[8][2];
#pragma unroll
            for (int mi = 0; mi < 2; mi++) {
                a[mi][0] = As[wm + mi * 16 + g][ks + tg];
                a[mi][1] = As[wm + mi * 16 + 8 + g][ks + tg];
                a[mi][2] = As[wm + mi * 16 + g][ks + 4 + tg];
                a[mi][3] = As[wm + mi * 16 + 8 + g][ks + 4 + tg];
            }
#pragma unroll
            for (int nj = 0; nj < 8; nj++) {
                b[nj][0] = Bs[ks + tg][wn + nj * 8 + g];
                b[nj][1] = Bs[ks + 4 + tg][wn + nj * 8 + g];
            }
#pragma unroll
            for (int mi = 0; mi < 2; mi++)
#pragma unroll
                for (int nj = 0; nj < 8; nj++)
                    mma_tf32(c[mi][nj], a[mi], b[nj]);
        }
        __syncthreads();
    }

#pragma unroll
    for (int mi = 0; mi < 2; mi++) {
#pragma unroll
        for (int nj = 0; nj < 8; nj++) {
            float* Cp = C + (size_t)(m0 + wm + mi * 16 + g) * N
                          + n0 + wn + nj * 8 + 2 * tg;
            *(float2*)Cp           = make_float2(c[mi][nj][0], c[mi][nj][1]);
            *(float2*)(Cp + 8 * N) = make_float2(c[mi][nj][2], c[mi][nj][3]);
        }
    }
}

// ---------------------------------------------------------------------------
// RoPE in-place, REVERSED rotation (verified), theta = 10000.
// ---------------------------------------------------------------------------
__global__ __launch_bounds__(256) void rope_kernel()
{
    int idx = blockIdx.x * blockDim.x + threadIdx.x;
    int i = idx & 63;
    int t = idx >> 6;
    int head = t % 40;
    int row = t / 40;
    if (row >= MROWS) return;

    const int* ids = (const int*)g_ptrs[5];
    int pos;
    if (ids) pos = ids[g_pos_is64 ? (row << 1) : row];
    else     pos = row & (SEQ - 1);

    float invf = expf(-ROPE_LN_OVER_HALF * (float)i);
    float ang = (float)pos * invf;
    float c, s;
    sincosf(ang, &c, &s);

    float* base;
    if (head < NHEADS) base = g_Q + (size_t)row * HID + head * HD;
    else               base = g_K + (size_t)row * KVD + (head - NHEADS) * HD;

    float x1 = base[i];
    float x2 = base[i + 64];
    base[i]      = x1 * c + x2 * s;   // reversed rotation (verified)
    base[i + 64] = x2 * c - x1 * s;
}

// ---------------------------------------------------------------------------
// Tensor-core flash attention. BM=64 queries/CTA, BN=64 keys/tile, d=128.
// 128 threads, 4 warps; warp w owns query rows [w*16, w*16+16), full BN.
// QK^T and P@V via mma m16n8k8 tf32. Online softmax within 4-lane quads.
// smem (uint): Qs[64][132], KsT[128][72], Vs[64][136], Ps[64][68].
// grid: (SEQ/64, BATCH*NHEADS); heavy CTAs scheduled first.
// ---------------------------------------------------------------------------
__global__ __launch_bounds__(128) void tc_flash_kernel()
{
    extern __shared__ unsigned smu[];
    unsigned* Qs  = smu;                 // [64][132]
    unsigned* KsT = Qs + 64 * 132;       // [128][72]  (transposed K)
    unsigned* Vs  = KsT + 128 * 72;      // [64][136]
    unsigned* Ps  = Vs + 64 * 136;       // [64][68]

    const int tid  = threadIdx.x;
    const int lane = tid & 31;
    const int wid  = tid >> 5;
    const int g    = lane >> 2;
    const int tg   = lane & 3;
    const int wm   = wid * 16;

    const int qt = gridDim.x - 1 - blockIdx.x;   // heavy CTAs first
    const int bh = blockIdx.y;
    const int b = bh >> 5, h = bh & 31, kvh = h >> 2;

    const float* Qg = g_Q + (size_t)(b * SEQ + qt * 64) * HID + h * HD;
    const float* Kg = g_K + (size_t)(b * SEQ) * KVD + kvh * HD;
    const float* Vg = g_V + (size_t)(b * SEQ) * KVD + kvh * HD;

    // Load Q tile (64x128) -> tf32 smem (coalesced gmem reads)
    for (int v = tid; v < 64 * 32; v += 128) {
        int r = v >> 5, c4 = (v & 31) << 2;
        float4 q = *(const float4*)(Qg + (size_t)r * HID + c4);
        Qs[r * 132 + c4 + 0] = f2tf32(q.x);
        Qs[r * 132 + c4 + 1] = f2tf32(q.y);
        Qs[r * 132 + c4 + 2] = f2tf32(q.z);
        Qs[r * 132 + c4 + 3] = f2tf32(q.w);
    }

    float O[16][4];
#pragma unroll
    for (int nj = 0; nj < 16; nj++)
#pragma unroll
        for (int e = 0; e < 4; e++) O[nj][e] = 0.f;
    float mrow[2] = {-CUDART_INF_F, -CUDART_INF_F};
    float lrow[2] = {0.f, 0.f};

    const int ntiles = qt + 1;
    const float scale = 0.08838834764831845f;   // 1/sqrt(128)
    const int row0 = qt * 64 + wm + g;          // rows row0, row0+8

    for (int kt = 0; kt < ntiles; kt++) {
        __syncthreads();   // prior tile reads done (first iter: Q stores done)

        // K tile transposed: row-scattered loads (L2-served), conflict-free STS
        for (int v = tid; v < 64 * 32; v += 128) {
            int r = v & 63, c4 = (v >> 6) << 2;
            float4 kx = *(const float4*)(Kg + (size_t)(kt * 64 + r) * KVD + c4);
            KsT[(c4 + 0) * 72 + r] = f2tf32(kx.x);
            KsT[(c4 + 1) * 72 + r] = f2tf32(kx.y);
            KsT[(c4 + 2) * 72 + r] = f2tf32(kx.z);
            KsT[(c4 + 3) * 72 + r] = f2tf32(kx.w);
        }
        // V tile (natural layout), coalesced
        for (int v = tid; v < 64 * 32; v += 128) {
            int r = v >> 5, c4 = (v & 31) << 2;
            float4 vx = *(const float4*)(Vg + (size_t)(kt * 64 + r) * KVD + c4);
            Vs[r * 136 + c4 + 0] = f2tf32(vx.x);
            Vs[r * 136 + c4 + 1] = f2tf32(vx.y);
            Vs[r * 136 + c4 + 2] = f2tf32(vx.z);
            Vs[r * 136 + c4 + 3] = f2tf32(vx.w);
        }
        __syncthreads();

        // ---- scores: S = Q @ K^T (m16 x n64, k=128) ----
        float c[8][4];
#pragma unroll
        for (int nj = 0; nj < 8; nj++)
#pragma unroll
            for (int e = 0; e < 4; e++) c[nj][e] = 0.f;

#pragma unroll
        for (int ks = 0; ks < 16; ks++) {
            unsigned a[4];
            a[0] = Qs[(wm + g) * 132 + ks * 8 + tg];
            a[1] = Qs[(wm + 8 + g) * 132 + ks * 8 + tg];
            a[2] = Qs[(wm + g) * 132 + ks * 8 + 4 + tg];
            a[3] = Qs[(wm + 8 + g) * 132 + ks * 8 + 4 + tg];
#pragma unroll
            for (int nj = 0; nj < 8; nj++) {
                unsigned bf[2];
                bf[0] = KsT[(ks * 8 + tg) * 72 + nj * 8 + g];
                bf[1] = KsT[(ks * 8 + 4 + tg) * 72 + nj * 8 + g];
                mma_tf32(c[nj], a, bf);
            }
        }

        // ---- mask + online softmax (per-row within 4-lane quad) ----
        const bool diag = (kt == qt);
        float mt[2] = {-CUDART_INF_F, -CUDART_INF_F};
#pragma unroll
        for (int nj = 0; nj < 8; nj++) {
#pragma unroll
            for (int e = 0; e < 4; e++) {
                int col = kt * 64 + nj * 8 + 2 * tg + (e & 1);
                int row = (e < 2) ? row0 : row0 + 8;
                float s = c[nj][e] * scale;
                if (diag && col > row) s = -CUDART_INF_F;
                c[nj][e] = s;
                mt[e >> 1] = fmaxf(mt[e >> 1], s);
            }
        }
#pragma unroll
        for (int i = 0; i < 2; i++) {
            mt[i] = fmaxf(mt[i], __shfl_xor_sync(0xffffffffu, mt[i], 1));
            mt[i] = fmaxf(mt[i], __shfl_xor_sync(0xffffffffu, mt[i], 2));
        }
        float mnew[2], alpha[2];
#pragma unroll
        for (int i = 0; i < 2; i++) {
            mnew[i] = fmaxf(mrow[i], mt[i]);
            alpha[i] = __expf(mrow[i] - mnew[i]);
            mrow[i] = mnew[i];
        }

        float ps[2] = {0.f, 0.f};
#pragma unroll
        for (int nj = 0; nj < 8; nj++) {
#pragma unroll
            for (int e = 0; e < 4; e++) {
                float p = __expf(c[nj][e] - mnew[e >> 1]);
                ps[e >> 1] += p;
                int prow = wm + g + ((e < 2) ? 0 : 8);
                Ps[prow * 68 + nj * 8 + 2 * tg + (e & 1)] = f2tf32(p);
            }
        }
#pragma unroll
        for (int i = 0; i < 2; i++) {
            ps[i] += __shfl_xor_sync(0xffffffffu, ps[i], 1);
            ps[i] += __shfl_xor_sync(0xffffffffu, ps[i], 2);
            lrow[i] = lrow[i] * alpha[i] + ps[i];
        }
#pragma unroll
        for (int nj = 0; nj < 16; nj++) {
            O[nj][0] *= alpha[0];
            O[nj][1] *= alpha[0];
            O[nj][2] *= alpha[1];
            O[nj][3] *= alpha[1];
        }

        __syncwarp();   // Ps rows of this warp visible to all its lanes

        // ---- PV: O += P (m16 x k64) @ V (k64 x n128) ----
#pragma unroll
        for (int ks = 0; ks < 8; ks++) {
            unsigned a[4];
            a[0] = Ps[(wm + g) * 68 + ks * 8 + tg];
            a[1] = Ps[(wm + 8 + g) * 68 + ks * 8 + tg];
            a[2] = Ps[(wm + g) * 68 + ks * 8 + 4 + tg];
            a[3] = Ps[(wm + 8 + g) * 68 + ks * 8 + 4 + tg];
#pragma unroll
            for (int nj = 0; nj < 16; nj++) {
                unsigned bf[2];
                bf[0] = Vs[(ks * 8 + tg) * 136 + nj * 8 + g];
                bf[1] = Vs[(ks * 8 + 4 + tg) * 136 + nj * 8 + g];
                mma_tf32(O[nj], a, bf);
            }
        }
    }

    // ---- epilogue ----
    float inv0 = 1.f / lrow[0];
    float inv1 = 1.f / lrow[1];
    float* Og0 = g_O + (size_t)(b * SEQ + row0) * HID + h * HD;
    float* Og1 = Og0 + (size_t)8 * HID;
#pragma unroll
    for (int nj = 0; nj < 16; nj++) {
        int col = nj * 8 + 2 * tg;
        *(float2*)(Og0 + col) = make_float2(O[nj][0] * inv0, O[nj][1] * inv0);
        *(float2*)(Og1 + col) = make_float2(O[nj][2] * inv1, O[nj][3] * inv1);
    }
}

// ---------------------------------------------------------------------------
extern "C" void kernel_launch(void* const* d_in, const int* in_sizes, int n_in,
                              void* d_out, int out_size)
{
    InArgs a;
    a.n = (n_in < 8) ? n_in : 8;
    for (int i = 0; i < 8; i++) {
        a.p[i]  = (i < n_in) ? (const float*)d_in[i] : nullptr;
        a.sz[i] = (i < n_in) ? in_sizes[i] : 0;
    }
    float* out = (float*)d_out;

    float *Q, *K, *V, *O;
    cudaGetSymbolAddress((void**)&Q, g_Q);
    cudaGetSymbolAddress((void**)&K, g_K);
    cudaGetSymbolAddress((void**)&V, g_V);
    cudaGetSymbolAddress((void**)&O, g_O);

    classify_kernel<<<1, 32>>>(a);

    tc_gemm_kernel<<<dim3(HID / 128, MROWS / 128), 256>>>(nullptr, 0, 1, Q, MROWS, HID, HID);
    tc_gemm_kernel<<<dim3(KVD / 128, MROWS / 128), 256>>>(nullptr, 0, 2, K, MROWS, KVD, HID);
    tc_gemm_kernel<<<dim3(KVD / 128, MROWS / 128), 256>>>(nullptr, 0, 3, V, MROWS, KVD, HID);

    rope_kernel<<<(MROWS * 40 * 64) / 256, 256>>>();

    constexpr int SMEM = (64 * 132 + 128 * 72 + 64 * 136 + 64 * 68) * 4;  // 122880
    cudaFuncSetAttribute(tc_flash_kernel, cudaFuncAttributeMaxDynamicSharedMemorySize, SMEM);
    tc_flash_kernel<<<dim3(SEQ / 64, BATCH * NHEADS), 128, SMEM>>>();

    tc_gemm_kernel<<<dim3(HID / 128, MROWS / 128), 256>>>(O, -1, 4, out, MROWS, HID, HID);
}